// round 2
// baseline (speedup 1.0000x reference)
#include <cuda_runtime.h>

// MeanAggregator: out[b, :] = mean_k table[neighs[b, k], :]
// neighs: [50000, 32] int (32 or 64 bit, auto-detected), table: [500000, 128] f32
// out: [50000, 128] f32. One warp per output node; lane l owns float4 cols [4l,4l+4).

#define BATCH   50000
#define DEGREE  32
#define D_FEAT  128
#define WARPS_PER_BLOCK 8
#define THREADS (WARPS_PER_BLOCK * 32)

__device__ int g_idx_is64;

// Detect index dtype: if the buffer is int64 (values < 500000 >= 0), every odd
// 32-bit word is zero. If int32, odd words are random indices (all-zero over
// 128 samples has probability ~ (1/500000)^128 ~ 0).
__global__ void detect_idx_dtype(const unsigned int* __restrict__ n32)
{
    bool all_zero = true;
    #pragma unroll
    for (int i = 1; i < 256; i += 2) {
        if (n32[i] != 0u) { all_zero = false; break; }
    }
    g_idx_is64 = all_zero ? 1 : 0;
}

__global__ __launch_bounds__(THREADS)
void mean_agg_kernel(const void* __restrict__ neighs_raw,
                     const float4* __restrict__ table,   // [500000, 32] float4
                     float4* __restrict__ out)           // [50000, 32] float4
{
    const int warp = (blockIdx.x * THREADS + threadIdx.x) >> 5;
    const int lane = threadIdx.x & 31;
    if (warp >= BATCH) return;

    // One coalesced load of this node's 32 indices (lane k holds index k).
    long long my_idx;
    if (g_idx_is64) {
        my_idx = ((const long long*)neighs_raw)[(size_t)warp * DEGREE + lane];
    } else {
        my_idx = (long long)((const int*)neighs_raw)[(size_t)warp * DEGREE + lane];
    }

    float4 acc = make_float4(0.f, 0.f, 0.f, 0.f);

    #pragma unroll 8
    for (int k = 0; k < DEGREE; ++k) {
        const long long idx = __shfl_sync(0xffffffffu, my_idx, k);
        const float4 v = __ldg(&table[(size_t)idx * (D_FEAT / 4) + lane]);
        acc.x += v.x; acc.y += v.y; acc.z += v.z; acc.w += v.w;
    }

    const float s = 1.0f / (float)DEGREE;
    acc.x *= s; acc.y *= s; acc.z *= s; acc.w *= s;
    out[(size_t)warp * (D_FEAT / 4) + lane] = acc;
}

extern "C" void kernel_launch(void* const* d_in, const int* in_sizes, int n_in,
                              void* d_out, int out_size)
{
    const void*   neighs = d_in[0];
    const float4* table  = (const float4*)d_in[1];
    float4*       out    = (float4*)d_out;

    detect_idx_dtype<<<1, 1>>>((const unsigned int*)neighs);

    const int blocks = (BATCH + WARPS_PER_BLOCK - 1) / WARPS_PER_BLOCK;
    mean_agg_kernel<<<blocks, THREADS>>>(neighs, table, out);
}

// round 4
// speedup vs baseline: 1.0220x; 1.0220x over previous
#include <cuda_runtime.h>

// MeanAggregator: out[b, :] = mean_k table[neighs[b, k], :]
// neighs: [50000, 32] int (32/64-bit auto-detected), table: [500000, 128] f32
// out: [50000, 128] f32.
// One warp per node. 256-bit gathers with L2 evict_last (legal form on sm_103a):
// lane = (half, sub): half = neighbor parity within iteration, sub = 32B slice.
// 16 iterations x 2 neighbors; final shfl_xor(16) fold; lanes 0-15 store row.

#define BATCH   50000
#define DEGREE  32
#define D_FEAT  128
#define WARPS_PER_BLOCK 8
#define THREADS (WARPS_PER_BLOCK * 32)

__device__ int g_idx_is64;

// If the buffer is int64 (values in [0, 500000)), every odd 32-bit word is 0.
// For int32 data the odd words are random indices: P(128 zeros) ~ 0.
__global__ void detect_idx_dtype(const unsigned int* __restrict__ n32)
{
    bool all_zero = true;
    #pragma unroll
    for (int i = 1; i < 256; i += 2) {
        if (n32[i] != 0u) { all_zero = false; break; }
    }
    g_idx_is64 = all_zero ? 1 : 0;
}

struct F8 { float v[8]; };

__device__ __forceinline__ F8 ldg_evict_last_v8(const float* p)
{
    F8 r;
    asm volatile(
        "ld.global.nc.L2::evict_last.v8.b32 {%0,%1,%2,%3,%4,%5,%6,%7}, [%8];"
        : "=f"(r.v[0]), "=f"(r.v[1]), "=f"(r.v[2]), "=f"(r.v[3]),
          "=f"(r.v[4]), "=f"(r.v[5]), "=f"(r.v[6]), "=f"(r.v[7])
        : "l"(p));
    return r;
}

__device__ __forceinline__ void stg_streaming_v4(float4* p, float4 v)
{
    asm volatile("st.global.cs.v4.f32 [%0], {%1,%2,%3,%4};"
                 :: "l"(p), "f"(v.x), "f"(v.y), "f"(v.z), "f"(v.w)
                 : "memory");
}

__global__ __launch_bounds__(THREADS)
void mean_agg_kernel(const void* __restrict__ neighs_raw,
                     const float* __restrict__ table,   // [500000, 128] f32
                     float4* __restrict__ out)          // [50000, 32] float4
{
    const int warp = (blockIdx.x * THREADS + threadIdx.x) >> 5;
    const int lane = threadIdx.x & 31;
    if (warp >= BATCH) return;

    const int half = lane >> 4;    // which neighbor of the pair this lane gathers
    const int sub  = lane & 15;    // which 32B slice of the 512B row

    // One coalesced streaming load of this node's 32 indices (lane k -> index k).
    long long my_idx;
    if (g_idx_is64) {
        my_idx = __ldcs(&((const long long*)neighs_raw)[(size_t)warp * DEGREE + lane]);
    } else {
        my_idx = (long long)__ldcs(&((const int*)neighs_raw)[(size_t)warp * DEGREE + lane]);
    }

    float acc[8] = {0.f, 0.f, 0.f, 0.f, 0.f, 0.f, 0.f, 0.f};

    #pragma unroll 4
    for (int k = 0; k < DEGREE / 2; ++k) {
        const long long idx = __shfl_sync(0xffffffffu, my_idx, 2 * k + half);
        const F8 r = ldg_evict_last_v8(&table[(size_t)idx * D_FEAT + sub * 8]);
        #pragma unroll
        for (int i = 0; i < 8; ++i) acc[i] += r.v[i];
    }

    // Fold the two halves: lane l and l^16 hold the same columns, disjoint k-sets.
    #pragma unroll
    for (int i = 0; i < 8; ++i)
        acc[i] += __shfl_xor_sync(0xffffffffu, acc[i], 16);

    if (half == 0) {
        const float s = 1.0f / (float)DEGREE;
        float4 lo = make_float4(acc[0] * s, acc[1] * s, acc[2] * s, acc[3] * s);
        float4 hi = make_float4(acc[4] * s, acc[5] * s, acc[6] * s, acc[7] * s);
        float4* dst = &out[(size_t)warp * (D_FEAT / 4) + sub * 2];
        stg_streaming_v4(dst, lo);
        stg_streaming_v4(dst + 1, hi);
    }
}

extern "C" void kernel_launch(void* const* d_in, const int* in_sizes, int n_in,
                              void* d_out, int out_size)
{
    const void*  neighs = d_in[0];
    const float* table  = (const float*)d_in[1];
    float4*      out    = (float4*)d_out;

    detect_idx_dtype<<<1, 1>>>((const unsigned int*)neighs);

    const int blocks = (BATCH + WARPS_PER_BLOCK - 1) / WARPS_PER_BLOCK;
    mean_agg_kernel<<<blocks, THREADS>>>(neighs, table, out);
}